// round 10
// baseline (speedup 1.0000x reference)
#include <cuda_runtime.h>
#include <cstdint>

#define NN 256      // batch
#define PP 128      // points per polygon (= segments)
#define TPB 512
#define NB  NN
#define MAGIC 12582912.0f // 2^23 + 2^22

__device__ float4 g_part[NN];
__device__ unsigned int g_cnt = 0;

__device__ __forceinline__ float smooth_l1(float p, float t) {
    float d = fabsf(p - t);
    return d < 0.25f ? 2.0f * d * d : d - 0.125f;   // BETA = 0.25
}

__device__ __forceinline__ unsigned long long pack2(float lo, float hi) {
    unsigned long long r;
    asm("mov.b64 %0, {%1, %2};" : "=l"(r)
        : "r"(__float_as_uint(lo)), "r"(__float_as_uint(hi)));
    return r;
}
__device__ __forceinline__ unsigned long long fma2(unsigned long long a,
                                                   unsigned long long b,
                                                   unsigned long long c) {
    unsigned long long r;
    asm("fma.rn.f32x2 %0, %1, %2, %3;" : "=l"(r) : "l"(a), "l"(b), "l"(c));
    return r;
}
__device__ __forceinline__ void unpack2(unsigned long long v, float& lo, float& hi) {
    unsigned int a, b;
    asm("mov.b64 {%0, %1}, %2;" : "=r"(a), "=r"(b) : "l"(v));
    lo = __uint_as_float(a); hi = __uint_as_float(b);
}

__global__ void __launch_bounds__(TPB, 2) dm_fused(
    const float* __restrict__ pred_c,
    const float* __restrict__ pred_o,
    const float* __restrict__ gt_c,
    const float* __restrict__ gt_k,
    const int*   __restrict__ gt_m,
    float*       __restrict__ out)
{
    // packed segment tables:
    //   T1 = (-2bx, -2dx, -2by, -2dy)   T2 = (|b|^2, 2 b·d, gamma, -0.5/gamma)
    __shared__ float4 s_T1[PP], s_T2[PP];
    __shared__ float4 s_pt[PP];                 // (-2px, -2py, |p|^2, 0)
    __shared__ float2 s_pred[PP], s_po[PP], s_gk[PP];
    __shared__ int    s_mk[PP];
    __shared__ float  s_red[4][16];
    __shared__ int    s_last;

    const int n = blockIdx.x;
    const int t = threadIdx.x;
    const int s = t & 15;           // seg-group 0..15  (seg = 16*j + s)
    const int g4 = (t >> 4) << 2;   // first of my 4 points

    // ---- parallel prologue: each warp-group loads one input stream ----
    {
        const int grp = t >> 7;     // 0..3
        const int q   = t & (PP - 1);
        const size_t off = (size_t)n * PP;
        if (grp == 0) {
            float2 pr = reinterpret_cast<const float2*>(pred_c)[off + q];
            s_pred[q] = pr;
            s_pt[q]   = make_float4(-2.0f * pr.x, -2.0f * pr.y,
                                    pr.x * pr.x + pr.y * pr.y, 0.0f);
        } else if (grp == 1) {
            s_po[q] = reinterpret_cast<const float2*>(pred_o)[off + q];
        } else if (grp == 2) {
            s_gk[q] = reinterpret_cast<const float2*>(gt_k)[off + q];
            s_mk[q] = gt_m[off + q];
        } else {
            const float2* gc2 = reinterpret_cast<const float2*>(gt_c) + off;
            float2 a = gc2[q];
            float2 b = gc2[(q + PP - 1) & (PP - 1)];
            float dx = (a.x - b.x) * 0.1f;
            float dy = (a.y - b.y) * 0.1f;
            float g2 = dx * dx + dy * dy;
            float inv = (g2 > 0.0f) ? (-0.5f / g2) : 0.0f;
            s_T1[q] = make_float4(-2.0f * b.x, -2.0f * dx, -2.0f * b.y, -2.0f * dy);
            s_T2[q] = make_float4(b.x * b.x + b.y * b.y,
                                  2.0f * (b.x * dx + b.y * dy), g2, inv);
        }
    }
    __syncthreads();

    // ---- item 1: 4 points x 8 segments per thread, key = score | seg ----
    float bk1[4];
    {
        unsigned long long pxx[4], pyy[4];
        #pragma unroll
        for (int u = 0; u < 4; ++u) {
            float2 pr = s_pred[g4 + u];
            pxx[u] = pack2(pr.x, pr.x);
            pyy[u] = pack2(pr.y, pr.y);
            bk1[u] = 3.4e38f;
        }
        #pragma unroll
        for (int j = 0; j < 8; ++j) {
            const int seg = j * 16 + s;
            const ulonglong2 q1 = *reinterpret_cast<const ulonglong2*>(&s_T1[seg]);
            const ulonglong2 q2 = *reinterpret_cast<const ulonglong2*>(&s_T2[seg]);
            float gam, inv; unpack2(q2.y, gam, inv);
            #pragma unroll
            for (int u = 0; u < 4; ++u) {
                unsigned long long ab = fma2(pyy[u], q1.y, q2.x);
                ab = fma2(pxx[u], q1.x, ab);
                float alpha, beta; unpack2(ab, alpha, beta);
                float kf = beta * inv;                      // vertex
                kf = fminf(fmaxf(kf, 0.0f), 9.0f);
                float mrd = kf + MAGIC;                     // magic round (RNE)
                float kr  = mrd - MAGIC;
                float v = fmaf(kr, fmaf(kr, gam, beta), alpha);
                float key = __uint_as_float(
                    (__float_as_uint(v) & 0xFFFFFF80u) | (unsigned)seg);
                bk1[u] = fminf(bk1[u], key);
            }
        }
    }

    // ---- item 2: 4 key points x 8 preds per thread ----
    float bk2[4];
    {
        float kx[4], ky[4];
        #pragma unroll
        for (int u = 0; u < 4; ++u) {
            float2 kk = s_gk[g4 + u];
            kx[u] = kk.x; ky[u] = kk.y;
            bk2[u] = 3.4e38f;
        }
        #pragma unroll
        for (int j = 0; j < 8; ++j) {
            const int pj = j * 16 + s;
            float4 E = s_pt[pj];
            #pragma unroll
            for (int u = 0; u < 4; ++u) {
                float d = fmaf(kx[u], E.x, fmaf(ky[u], E.y, E.z));
                float key = __uint_as_float(
                    (__float_as_uint(d) & 0xFFFFFF80u) | (unsigned)pj);
                bk2[u] = fminf(bk2[u], key);
            }
        }
    }

    // ---- in-warp combine over the 16 seg-groups (keys unique -> fminf) ----
    #pragma unroll
    for (int o = 1; o <= 8; o <<= 1) {
        #pragma unroll
        for (int u = 0; u < 4; ++u) {
            bk1[u] = fminf(bk1[u], __shfl_xor_sync(0xffffffffu, bk1[u], o));
            bk2[u] = fminf(bk2[u], __shfl_xor_sync(0xffffffffu, bk2[u], o));
        }
    }

    // ---- split tail: lanes s<4 -> item1 loss, 4<=s<8 -> item2 loss ----
    float s1 = 0.0f, c1 = 0.0f, s2 = 0.0f, c2 = 0.0f;
    if (s < 4) {
        const int u  = s;
        const int pt = g4 + u;
        float key = (u & 2) ? ((u & 1) ? bk1[3] : bk1[2])
                            : ((u & 1) ? bk1[1] : bk1[0]);
        int seg = __float_as_int(key) & 0x7F;
        float4 T1 = s_T1[seg];                  // (-2bx,-2dx,-2by,-2dy)
        float4 T2 = s_T2[seg];                  // (|b|^2, 2b·d, gam, inv)
        float2 pr = s_pred[pt];
        // recompute exact k for the winning segment
        float beta = fmaf(pr.x, T1.y, fmaf(pr.y, T1.w, T2.y));
        float kf = fminf(fmaxf(beta * T2.w, 0.0f), 9.0f);
        kf = (kf + MAGIC) - MAGIC;              // RNE round
        float tx = -0.5f * fmaf(kf, T1.y, T1.x);
        float ty = -0.5f * fmaf(kf, T1.w, T1.z);
        float dxx = pr.x - tx, dyy = pr.y - ty;
        float d2 = dxx * dxx + dyy * dyy;       // exact matched dist^2
        if (d2 <= 1.0e6f) {
            float2 mo = s_po[pt];
            float ox = (tx - pr.x) * 0.25f;
            float oy = (ty - pr.y) * 0.25f;
            s1 = smooth_l1(mo.x, ox) + smooth_l1(mo.y, oy);
            c1 = 1.0f;
        }
    } else if (s < 8) {
        const int u  = s - 4;
        const int pt = g4 + u;
        float key = (u & 2) ? ((u & 1) ? bk2[3] : bk2[2])
                            : ((u & 1) ? bk2[1] : bk2[0]);
        int j2m = __float_as_int(key) & 0x7F;
        float2 kk = s_gk[pt];
        float2 pg = s_pred[j2m];
        float dxx = kk.x - pg.x, dyy = kk.y - pg.y;
        float d2 = dxx * dxx + dyy * dyy;       // exact matched dist^2
        if (s_mk[pt] && d2 <= 1.0e6f) {
            float2 og = s_po[j2m];
            float ox = dxx * 0.25f;
            float oy = dyy * 0.25f;
            s2 = smooth_l1(og.x, ox) + smooth_l1(og.y, oy);
            c2 = 1.0f;
        }
    }

    // ---- deterministic block reduction over all 16 warps ----
    #pragma unroll
    for (int o = 16; o > 0; o >>= 1) {
        s1 += __shfl_down_sync(0xffffffffu, s1, o);
        c1 += __shfl_down_sync(0xffffffffu, c1, o);
        s2 += __shfl_down_sync(0xffffffffu, s2, o);
        c2 += __shfl_down_sync(0xffffffffu, c2, o);
    }
    const int w = t >> 5, l = t & 31;
    if (l == 0) {
        s_red[0][w] = s1; s_red[1][w] = c1;
        s_red[2][w] = s2; s_red[3][w] = c2;
    }
    __syncthreads();
    if (t == 0) {
        float a0 = 0.f, a1 = 0.f, a2 = 0.f, a3 = 0.f;
        #pragma unroll
        for (int i = 0; i < 16; ++i) {
            a0 += s_red[0][i]; a1 += s_red[1][i];
            a2 += s_red[2][i]; a3 += s_red[3][i];
        }
        g_part[n] = make_float4(a0, a1, a2, a3);
        __threadfence();
        unsigned int v = atomicAdd(&g_cnt, 1u);
        s_last = (v == (unsigned)(NB - 1));
    }
    __syncthreads();

    // ---- last block: fixed-order final reduction (bitwise deterministic) ----
    if (s_last) {
        float f1 = 0.f, f2 = 0.f, f3 = 0.f, f4 = 0.f;
        if (t < NN) {
            float4 v = g_part[t];
            f1 = v.x; f2 = v.y; f3 = v.z; f4 = v.w;
        }
        #pragma unroll
        for (int o = 16; o > 0; o >>= 1) {
            f1 += __shfl_down_sync(0xffffffffu, f1, o);
            f2 += __shfl_down_sync(0xffffffffu, f2, o);
            f3 += __shfl_down_sync(0xffffffffu, f3, o);
            f4 += __shfl_down_sync(0xffffffffu, f4, o);
        }
        __syncthreads();
        if (l == 0) {
            s_red[0][w] = f1; s_red[1][w] = f2;
            s_red[2][w] = f3; s_red[3][w] = f4;
        }
        __syncthreads();
        if (t == 0) {
            float t1 = 0.f, t2 = 0.f, t3 = 0.f, t4 = 0.f;
            #pragma unroll
            for (int i = 0; i < 16; ++i) {
                t1 += s_red[0][i]; t2 += s_red[1][i];
                t3 += s_red[2][i]; t4 += s_red[3][i];
            }
            float loss1 = (t1 / fmaxf(t2 * 2.0f, 1.0f)) * 0.5f;  // * (1 - KEY_W)
            float loss2 = (t3 / fmaxf(t4 * 2.0f, 1.0f)) * 0.5f;  // * KEY_W
            out[0] = loss1 + loss2;
            g_cnt = 0;   // reset for next graph replay
        }
    }
}

extern "C" void kernel_launch(void* const* d_in, const int* in_sizes, int n_in,
                              void* d_out, int out_size)
{
    const float* pred_c = (const float*)d_in[0];
    const float* pred_o = (const float*)d_in[1];
    const float* gt_c   = (const float*)d_in[2];
    const float* gt_k   = (const float*)d_in[3];
    const int*   gt_m   = (const int*)d_in[4];

    dm_fused<<<NB, TPB>>>(pred_c, pred_o, gt_c, gt_k, gt_m, (float*)d_out);
}

// round 12
// speedup vs baseline: 1.1373x; 1.1373x over previous
#include <cuda_runtime.h>
#include <cstdint>

#define NN 256      // batch
#define PP 128      // points per polygon (= segments)
#define TPB 512
#define NB  NN
#define MAGIC 12582912.0f // 2^23 + 2^22

__device__ float4 g_part[NN];
__device__ unsigned int g_cnt = 0;

__device__ __forceinline__ float smooth_l1(float p, float t) {
    float d = fabsf(p - t);
    return d < 0.25f ? 2.0f * d * d : d - 0.125f;   // BETA = 0.25
}

__device__ __forceinline__ unsigned long long pack2(float lo, float hi) {
    unsigned long long r;
    asm("mov.b64 %0, {%1, %2};" : "=l"(r)
        : "r"(__float_as_uint(lo)), "r"(__float_as_uint(hi)));
    return r;
}
__device__ __forceinline__ unsigned long long fma2(unsigned long long a,
                                                   unsigned long long b,
                                                   unsigned long long c) {
    unsigned long long r;
    asm("fma.rn.f32x2 %0, %1, %2, %3;" : "=l"(r) : "l"(a), "l"(b), "l"(c));
    return r;
}
__device__ __forceinline__ void unpack2(unsigned long long v, float& lo, float& hi) {
    unsigned int a, b;
    asm("mov.b64 {%0, %1}, %2;" : "=r"(a), "=r"(b) : "l"(v));
    lo = __uint_as_float(a); hi = __uint_as_float(b);
}

__global__ void __launch_bounds__(TPB, 2) dm_fused(
    const float* __restrict__ pred_c,
    const float* __restrict__ pred_o,
    const float* __restrict__ gt_c,
    const float* __restrict__ gt_k,
    const int*   __restrict__ gt_m,
    float*       __restrict__ out)
{
    // packed segment tables:
    //   T1 = (-2bx, -2dx, -2by, -2dy)   T2 = (|b|^2, 2 b·d, gamma, -0.5/gamma)
    __shared__ float4 s_T1[PP], s_T2[PP];
    __shared__ float4 s_pt[PP];                 // (-2px, -2py, |p|^2, 0)
    __shared__ float2 s_pred[PP], s_po[PP], s_gk[PP];
    __shared__ int    s_mk[PP];
    __shared__ float  s_red[4][16];
    __shared__ int    s_last;

    const int n = blockIdx.x;
    const int t = threadIdx.x;
    const int s = t & 15;           // seg-group 0..15  (seg = 16*j + s)
    const int g4 = (t >> 4) << 2;   // first of my 4 points

    // ---- parallel prologue: each warp-group loads one input stream ----
    {
        const int grp = t >> 7;     // 0..3
        const int q   = t & (PP - 1);
        const size_t off = (size_t)n * PP;
        if (grp == 0) {
            float2 pr = reinterpret_cast<const float2*>(pred_c)[off + q];
            s_pred[q] = pr;
            s_pt[q]   = make_float4(-2.0f * pr.x, -2.0f * pr.y,
                                    pr.x * pr.x + pr.y * pr.y, 0.0f);
        } else if (grp == 1) {
            s_po[q] = reinterpret_cast<const float2*>(pred_o)[off + q];
        } else if (grp == 2) {
            s_gk[q] = reinterpret_cast<const float2*>(gt_k)[off + q];
            s_mk[q] = gt_m[off + q];
        } else {
            const float2* gc2 = reinterpret_cast<const float2*>(gt_c) + off;
            float2 a = gc2[q];
            float2 b = gc2[(q + PP - 1) & (PP - 1)];
            float dx = (a.x - b.x) * 0.1f;
            float dy = (a.y - b.y) * 0.1f;
            float g2 = dx * dx + dy * dy;
            float inv = (g2 > 0.0f) ? (-0.5f / g2) : 0.0f;
            s_T1[q] = make_float4(-2.0f * b.x, -2.0f * dx, -2.0f * b.y, -2.0f * dy);
            s_T2[q] = make_float4(b.x * b.x + b.y * b.y,
                                  2.0f * (b.x * dx + b.y * dy), g2, inv);
        }
    }
    __syncthreads();

    // ---- fused scan: 4 points x 8 segments, item1 + item2 interleaved ----
    float bk1[4], bk2[4];
    {
        unsigned long long pxx[4], pyy[4];
        float kx[4], ky[4];
        #pragma unroll
        for (int u = 0; u < 4; ++u) {
            float2 pr = s_pred[g4 + u];
            pxx[u] = pack2(pr.x, pr.x);
            pyy[u] = pack2(pr.y, pr.y);
            bk1[u] = 3.4e38f;
            float2 kk = s_gk[g4 + u];
            kx[u] = kk.x; ky[u] = kk.y;
            bk2[u] = 3.4e38f;
        }
        #pragma unroll
        for (int j = 0; j < 8; ++j) {
            const int seg = j * 16 + s;
            const ulonglong2 q1 = *reinterpret_cast<const ulonglong2*>(&s_T1[seg]);
            const ulonglong2 q2 = *reinterpret_cast<const ulonglong2*>(&s_T2[seg]);
            const float4 E = s_pt[seg];
            float gam, inv; unpack2(q2.y, gam, inv);
            #pragma unroll
            for (int u = 0; u < 4; ++u) {
                // ---- item 1 candidate ----
                unsigned long long ab = fma2(pyy[u], q1.y, q2.x);
                ab = fma2(pxx[u], q1.x, ab);
                float alpha, beta; unpack2(ab, alpha, beta);
                float kf = beta * inv;                      // vertex
                kf = fminf(fmaxf(kf, 0.0f), 9.0f);
                float mrd = kf + MAGIC;                     // magic round (RNE)
                float kr  = mrd - MAGIC;
                float v = fmaf(kr, fmaf(kr, gam, beta), alpha);
                float key1 = __uint_as_float(
                    (__float_as_uint(v) & 0xFFFFFF80u) | (unsigned)seg);
                bk1[u] = fminf(bk1[u], key1);
                // ---- item 2 candidate (independent chain) ----
                float d = fmaf(kx[u], E.x, fmaf(ky[u], E.y, E.z));
                float key2 = __uint_as_float(
                    (__float_as_uint(d) & 0xFFFFFF80u) | (unsigned)seg);
                bk2[u] = fminf(bk2[u], key2);
            }
        }
    }

    // ---- in-warp combine over the 16 seg-groups (keys unique -> fminf) ----
    #pragma unroll
    for (int o = 1; o <= 8; o <<= 1) {
        #pragma unroll
        for (int u = 0; u < 4; ++u) {
            bk1[u] = fminf(bk1[u], __shfl_xor_sync(0xffffffffu, bk1[u], o));
            bk2[u] = fminf(bk2[u], __shfl_xor_sync(0xffffffffu, bk2[u], o));
        }
    }

    // ---- split tail: lanes s<4 -> item1 loss, 4<=s<8 -> item2 loss ----
    // packed per-row counter: cp = c1 + 512*c2 (per-row c1,c2 <= 128 -> exact)
    float s1 = 0.0f, s2 = 0.0f, cp = 0.0f;
    if (s < 4) {
        const int u  = s;
        const int pt = g4 + u;
        float key = (u & 2) ? ((u & 1) ? bk1[3] : bk1[2])
                            : ((u & 1) ? bk1[1] : bk1[0]);
        int seg = __float_as_int(key) & 0x7F;
        float4 T1 = s_T1[seg];                  // (-2bx,-2dx,-2by,-2dy)
        float4 T2 = s_T2[seg];                  // (|b|^2, 2b·d, gam, inv)
        float2 pr = s_pred[pt];
        // recompute exact k for the winning segment
        float beta = fmaf(pr.x, T1.y, fmaf(pr.y, T1.w, T2.y));
        float kf = fminf(fmaxf(beta * T2.w, 0.0f), 9.0f);
        kf = (kf + MAGIC) - MAGIC;              // RNE round
        float tx = -0.5f * fmaf(kf, T1.y, T1.x);
        float ty = -0.5f * fmaf(kf, T1.w, T1.z);
        float dxx = pr.x - tx, dyy = pr.y - ty;
        float d2 = dxx * dxx + dyy * dyy;       // exact matched dist^2
        if (d2 <= 1.0e6f) {
            float2 mo = s_po[pt];
            float ox = (tx - pr.x) * 0.25f;
            float oy = (ty - pr.y) * 0.25f;
            s1 = smooth_l1(mo.x, ox) + smooth_l1(mo.y, oy);
            cp = 1.0f;
        }
    } else if (s < 8) {
        const int u  = s - 4;
        const int pt = g4 + u;
        float key = (u & 2) ? ((u & 1) ? bk2[3] : bk2[2])
                            : ((u & 1) ? bk2[1] : bk2[0]);
        int j2m = __float_as_int(key) & 0x7F;
        float2 kk = s_gk[pt];
        float2 pg = s_pred[j2m];
        float dxx = kk.x - pg.x, dyy = kk.y - pg.y;
        float d2 = dxx * dxx + dyy * dyy;       // exact matched dist^2
        if (s_mk[pt] && d2 <= 1.0e6f) {
            float2 og = s_po[j2m];
            float ox = dxx * 0.25f;
            float oy = dyy * 0.25f;
            s2 = smooth_l1(og.x, ox) + smooth_l1(og.y, oy);
            cp = 512.0f;
        }
    }

    // ---- deterministic block reduction (3 chains) ----
    #pragma unroll
    for (int o = 16; o > 0; o >>= 1) {
        s1 += __shfl_down_sync(0xffffffffu, s1, o);
        s2 += __shfl_down_sync(0xffffffffu, s2, o);
        cp += __shfl_down_sync(0xffffffffu, cp, o);
    }
    const int w = t >> 5, l = t & 31;
    if (l == 0) {
        s_red[0][w] = s1; s_red[1][w] = s2; s_red[2][w] = cp;
    }
    __syncthreads();
    if (t == 0) {
        float a0 = 0.f, a1 = 0.f, a2 = 0.f;
        #pragma unroll
        for (int i = 0; i < 16; ++i) {
            a0 += s_red[0][i]; a1 += s_red[1][i]; a2 += s_red[2][i];
        }
        // unpack per-row counters BEFORE the cross-row sum (a2 <= 65664, exact)
        float c2 = floorf(a2 * (1.0f / 512.0f));
        float c1 = a2 - 512.0f * c2;
        g_part[n] = make_float4(a0, a1, c1, c2);
        __threadfence();
        unsigned int v = atomicAdd(&g_cnt, 1u);
        s_last = (v == (unsigned)(NB - 1));
    }
    __syncthreads();

    // ---- last block: fixed-order final reduction (bitwise deterministic) ----
    if (s_last) {
        float f1 = 0.f, f2 = 0.f, f3 = 0.f, f4 = 0.f;
        if (t < NN) {
            float4 v = g_part[t];
            f1 = v.x; f2 = v.y; f3 = v.z; f4 = v.w;
        }
        #pragma unroll
        for (int o = 16; o > 0; o >>= 1) {
            f1 += __shfl_down_sync(0xffffffffu, f1, o);
            f2 += __shfl_down_sync(0xffffffffu, f2, o);
            f3 += __shfl_down_sync(0xffffffffu, f3, o);
            f4 += __shfl_down_sync(0xffffffffu, f4, o);
        }
        __syncthreads();
        if (l == 0) {
            s_red[0][w] = f1; s_red[1][w] = f2;
            s_red[2][w] = f3; s_red[3][w] = f4;
        }
        __syncthreads();
        if (t == 0) {
            float t1 = 0.f, t2 = 0.f, t3 = 0.f, t4 = 0.f;
            #pragma unroll
            for (int i = 0; i < 16; ++i) {
                t1 += s_red[0][i]; t2 += s_red[1][i];
                t3 += s_red[2][i]; t4 += s_red[3][i];
            }
            float loss1 = (t1 / fmaxf(t3 * 2.0f, 1.0f)) * 0.5f;  // * (1 - KEY_W)
            float loss2 = (t2 / fmaxf(t4 * 2.0f, 1.0f)) * 0.5f;  // * KEY_W
            out[0] = loss1 + loss2;
            g_cnt = 0;   // reset for next graph replay
        }
    }
}

extern "C" void kernel_launch(void* const* d_in, const int* in_sizes, int n_in,
                              void* d_out, int out_size)
{
    const float* pred_c = (const float*)d_in[0];
    const float* pred_o = (const float*)d_in[1];
    const float* gt_c   = (const float*)d_in[2];
    const float* gt_k   = (const float*)d_in[3];
    const int*   gt_m   = (const int*)d_in[4];

    dm_fused<<<NB, TPB>>>(pred_c, pred_o, gt_c, gt_k, gt_m, (float*)d_out);
}